// round 2
// baseline (speedup 1.0000x reference)
#include <cuda_runtime.h>

#define NN 1024
#define DD 128

// ---------------- scratch (no allocations allowed) ----------------
__device__ float g_q[NN * DD];
__device__ float g_k[NN * DD];
__device__ float g_att[NN * DD];
__device__ float g_gi[NN * 3 * DD];

// ---------------- helpers ----------------
__device__ __forceinline__ float tanh_apx(float x) {
    float y;
    asm("tanh.approx.f32 %0, %1;" : "=f"(y) : "f"(x));
    return y;
}

__device__ __forceinline__ unsigned long long ffma2(unsigned long long a,
                                                    unsigned long long b,
                                                    unsigned long long c) {
    unsigned long long d;
    asm("fma.rn.f32x2 %0, %1, %2, %3;" : "=l"(d) : "l"(a), "l"(b), "l"(c));
    return d;
}

__device__ __forceinline__ float f2lo(unsigned long long a) {
    return __uint_as_float((unsigned)(a & 0xffffffffull));
}
__device__ __forceinline__ float f2hi(unsigned long long a) {
    return __uint_as_float((unsigned)(a >> 32));
}

// accurate sigmoid/tanh for the GRU (errors compound over 1024 steps)
__device__ __forceinline__ float sig_acc(float x) {
    float e = __expf(-x);
    return __fdividef(1.0f, 1.0f + e);
}
__device__ __forceinline__ float tanh_acc(float x) {
    float e = __expf(-2.0f * x);
    return __fdividef(1.0f - e, 1.0f + e);
}

__device__ __forceinline__ float block_reduce_max(float v) {
    __shared__ float red[8];
    #pragma unroll
    for (int o = 16; o; o >>= 1) v = fmaxf(v, __shfl_xor_sync(0xffffffffu, v, o));
    if ((threadIdx.x & 31) == 0) red[threadIdx.x >> 5] = v;
    __syncthreads();
    float r = red[0];
    #pragma unroll
    for (int i = 1; i < 8; i++) r = fmaxf(r, red[i]);
    __syncthreads();
    return r;
}

__device__ __forceinline__ float block_reduce_sum(float v) {
    __shared__ float red[8];
    #pragma unroll
    for (int o = 16; o; o >>= 1) v += __shfl_xor_sync(0xffffffffu, v, o);
    if ((threadIdx.x & 31) == 0) red[threadIdx.x >> 5] = v;
    __syncthreads();
    float r = red[0];
    #pragma unroll
    for (int i = 1; i < 8; i++) r += red[i];
    __syncthreads();
    return r;
}

// ---------------- kernel 1: q = X@Wq^T, k = X@Wk^T ----------------
// 256 threads: s = tid>>7 selects q vs k, d = tid&127 the output column.
// 8 rows of X staged in smem per CTA.
__global__ void __launch_bounds__(256) qk_kernel(const float* __restrict__ X,
                                                 const float* __restrict__ Wq,
                                                 const float* __restrict__ Wk) {
    __shared__ __align__(16) float xs[8][DD];
    const int n0 = blockIdx.x * 8;
    const int tid = threadIdx.x;
    for (int idx = tid; idx < 8 * DD; idx += 256)
        xs[idx >> 7][idx & 127] = X[(n0 + (idx >> 7)) * DD + (idx & 127)];
    __syncthreads();

    const int s = tid >> 7;
    const int d = tid & 127;
    const float4* W4 = (const float4*)((s ? Wk : Wq) + d * DD);
    float acc[8];
    #pragma unroll
    for (int r = 0; r < 8; r++) acc[r] = 0.0f;

    #pragma unroll 8
    for (int c = 0; c < 32; c++) {
        float4 w = W4[c];
        #pragma unroll
        for (int r = 0; r < 8; r++) {
            float4 x = *(const float4*)&xs[r][c * 4];
            acc[r] += w.x * x.x + w.y * x.y + w.z * x.z + w.w * x.w;
        }
    }
    float* dst = s ? g_k : g_q;
    #pragma unroll
    for (int r = 0; r < 8; r++) dst[(n0 + r) * DD + d] = acc[r];
}

// ---------------- kernel 2: attention (scores + softmax + att) ----------------
// One CTA per 4 query rows (256 CTAs, 256 threads). Suffix mask j >= i.
__global__ void __launch_bounds__(256) att_kernel(const float* __restrict__ X,
                                                  const float* __restrict__ v) {
    __shared__ __align__(16) float q_s[4][DD];
    __shared__ __align__(16) float v_s[DD];
    __shared__ float sc[4][NN];     // scores, then softmax weights
    __shared__ float inv_s[4];
    __shared__ float part[4][DD];

    const int i0 = blockIdx.x * 4;
    const int tid = threadIdx.x;

    for (int idx = tid; idx < 4 * DD; idx += 256)
        q_s[idx >> 7][idx & 127] = g_q[(i0 + (idx >> 7)) * DD + (idx & 127)];
    if (tid < DD) v_s[tid] = v[tid];
    __syncthreads();

    // ---- phase A: scores[r][j] = sum_d v[d] * tanh(q_r[d] + k_j[d]) ----
    for (int j = i0 + tid; j < NN; j += 256) {
        const float4* kr = (const float4*)(g_k + j * DD);
        float a0 = 0.f, a1 = 0.f, a2 = 0.f, a3 = 0.f;
        #pragma unroll 4
        for (int c = 0; c < 32; c++) {
            float4 kk = kr[c];
            float4 vv = *(const float4*)&v_s[c * 4];
            float4 q0 = *(const float4*)&q_s[0][c * 4];
            float4 q1 = *(const float4*)&q_s[1][c * 4];
            float4 q2 = *(const float4*)&q_s[2][c * 4];
            float4 q3 = *(const float4*)&q_s[3][c * 4];
            a0 += vv.x * tanh_apx(q0.x + kk.x) + vv.y * tanh_apx(q0.y + kk.y)
                + vv.z * tanh_apx(q0.z + kk.z) + vv.w * tanh_apx(q0.w + kk.w);
            a1 += vv.x * tanh_apx(q1.x + kk.x) + vv.y * tanh_apx(q1.y + kk.y)
                + vv.z * tanh_apx(q1.z + kk.z) + vv.w * tanh_apx(q1.w + kk.w);
            a2 += vv.x * tanh_apx(q2.x + kk.x) + vv.y * tanh_apx(q2.y + kk.y)
                + vv.z * tanh_apx(q2.z + kk.z) + vv.w * tanh_apx(q2.w + kk.w);
            a3 += vv.x * tanh_apx(q3.x + kk.x) + vv.y * tanh_apx(q3.y + kk.y)
                + vv.z * tanh_apx(q3.z + kk.z) + vv.w * tanh_apx(q3.w + kk.w);
        }
        const int jj = j - i0;
        sc[0][jj] = a0; sc[1][jj] = a1; sc[2][jj] = a2; sc[3][jj] = a3;
    }
    __syncthreads();

    // ---- phase B: per-row softmax over the suffix ----
    const int L = NN - i0;
    for (int r = 0; r < 4; r++) {
        float m = -1e30f;
        for (int idx = tid; idx < L; idx += 256) m = fmaxf(m, sc[r][idx]);
        const float bm = block_reduce_max(m);
        float ssum = 0.f;
        for (int idx = tid; idx < L; idx += 256) {
            float e = (idx < r) ? 0.0f : __expf(sc[r][idx] - bm); // enforce j >= i0+r
            sc[r][idx] = e;
            ssum += e;
        }
        const float bs = block_reduce_sum(ssum);
        if (tid == 0) inv_s[r] = 1.0f / bs;
    }
    __syncthreads();

    // ---- phase C: att[r][d] = (1/sum) * sum_j w[r][j] * X[j][d] ----
    const int d = tid & 127;
    const int s2 = tid >> 7;
    float a[4] = {0.f, 0.f, 0.f, 0.f};
    for (int j = i0 + s2; j < NN; j += 2) {
        const float x = X[j * DD + d];
        const int jj = j - i0;
        a[0] += sc[0][jj] * x;
        a[1] += sc[1][jj] * x;
        a[2] += sc[2][jj] * x;
        a[3] += sc[3][jj] * x;
    }
    if (s2) {
        #pragma unroll
        for (int r = 0; r < 4; r++) part[r][d] = a[r];
    }
    __syncthreads();
    if (!s2) {
        #pragma unroll
        for (int r = 0; r < 4; r++)
            g_att[(i0 + r) * DD + d] = (a[r] + part[r][d]) * inv_s[r];
    }
}

// ---------------- kernel 3: gi = [X, att] @ w_ih^T + b_ih ----------------
// 384 threads (one per output gate), 8 rows staged per CTA.
__global__ void __launch_bounds__(384) gi_kernel(const float* __restrict__ X,
                                                 const float* __restrict__ w_ih,
                                                 const float* __restrict__ b_ih) {
    __shared__ __align__(16) float in_s[8][2 * DD];
    const int n0 = blockIdx.x * 8;
    const int tid = threadIdx.x;
    for (int idx = tid; idx < 8 * 2 * DD; idx += 384) {
        const int n = idx >> 8, e = idx & 255;
        in_s[n][e] = (e < DD) ? X[(n0 + n) * DD + e] : g_att[(n0 + n) * DD + (e - DD)];
    }
    __syncthreads();

    const float4* w4 = (const float4*)(w_ih + tid * (2 * DD));
    float acc[8];
    #pragma unroll
    for (int r = 0; r < 8; r++) acc[r] = 0.0f;

    #pragma unroll 4
    for (int c = 0; c < 64; c++) {
        float4 w = w4[c];
        #pragma unroll
        for (int r = 0; r < 8; r++) {
            float4 iv = *(const float4*)&in_s[r][c * 4];
            acc[r] += w.x * iv.x + w.y * iv.y + w.z * iv.z + w.w * iv.w;
        }
    }
    const float b = b_ih[tid];
    #pragma unroll
    for (int r = 0; r < 8; r++) g_gi[(n0 + r) * 384 + tid] = acc[r] + b;
}

// ---------------- kernel 4: sequential GRU (single CTA, FFMA2) ----------------
// Thread t owns w_hh row t in registers (64 packed f32x2 pairs).
__global__ void __launch_bounds__(384, 1) gru_kernel(const float* __restrict__ w_hh,
                                                     const float* __restrict__ b_hh,
                                                     float* __restrict__ out) {
    __shared__ __align__(16) float h_s[DD];
    __shared__ float gh_s[384];

    const int t = threadIdx.x;
    unsigned long long w2[64];
    const unsigned long long* wp = (const unsigned long long*)(w_hh + t * DD);
    #pragma unroll
    for (int i = 0; i < 64; i++) w2[i] = wp[i];
    const float bh = b_hh[t];

    if (t < DD) h_s[t] = 0.0f;
    __syncthreads();

    const ulonglong2* h2 = (const ulonglong2*)h_s;

    for (int step = 0; step < NN; step++) {
        // prefetch this step's input-gate row early (overlaps LDG latency with matvec)
        float ir = 0.f, iz = 0.f, in_ = 0.f;
        if (t < DD) {
            const float* g = g_gi + step * 384;
            ir = g[t]; iz = g[t + DD]; in_ = g[t + 2 * DD];
        }

        // gh[t] = b_hh[t] + w_hh[t,:] . h   (packed f32x2 MACs)
        unsigned long long a0 = 0ull, a1 = 0ull, a2 = 0ull, a3 = 0ull;
        #pragma unroll
        for (int i = 0; i < 16; i++) {
            ulonglong2 hA = h2[2 * i];
            ulonglong2 hB = h2[2 * i + 1];
            a0 = ffma2(w2[4 * i + 0], hA.x, a0);
            a1 = ffma2(w2[4 * i + 1], hA.y, a1);
            a2 = ffma2(w2[4 * i + 2], hB.x, a2);
            a3 = ffma2(w2[4 * i + 3], hB.y, a3);
        }
        const float s = ((f2lo(a0) + f2hi(a0)) + (f2lo(a1) + f2hi(a1)))
                      + ((f2lo(a2) + f2hi(a2)) + (f2lo(a3) + f2hi(a3))) + bh;
        gh_s[t] = s;
        __syncthreads();

        if (t < DD) {
            const float r   = sig_acc(ir + s);            // gh_s[t] == s for t < 128
            const float z   = sig_acc(iz + gh_s[t + DD]);
            const float nst = tanh_acc(in_ + r * gh_s[t + 2 * DD]);
            const float ho  = h_s[t];
            const float hv  = (1.0f - z) * nst + z * ho;
            out[step * DD + t] = hv;
            h_s[t] = hv;
        }
        __syncthreads();
    }
}

// ---------------- launch ----------------
extern "C" void kernel_launch(void* const* d_in, const int* in_sizes, int n_in,
                              void* d_out, int out_size) {
    const float* X    = (const float*)d_in[0];
    const float* Wq   = (const float*)d_in[1];
    const float* Wk   = (const float*)d_in[2];
    const float* v    = (const float*)d_in[3];
    const float* w_ih = (const float*)d_in[4];
    const float* w_hh = (const float*)d_in[5];
    const float* b_ih = (const float*)d_in[6];
    const float* b_hh = (const float*)d_in[7];
    float* out = (float*)d_out;

    qk_kernel<<<NN / 8, 256>>>(X, Wq, Wk);
    att_kernel<<<NN / 4, 256>>>(X, v);
    gi_kernel<<<NN / 8, 384>>>(X, w_ih, b_ih);
    gru_kernel<<<1, 384>>>(w_hh, b_hh, out);
}

// round 4
// speedup vs baseline: 1.0120x; 1.0120x over previous
#include <cuda_runtime.h>

#define NN 1024
#define DD 128

// ---------------- scratch (no allocations allowed) ----------------
__device__ float g_q[NN * DD];
__device__ float g_k[NN * DD];
__device__ float g_att[NN * DD];
__device__ float g_gi[NN * 3 * DD];

// ---------------- helpers ----------------
__device__ __forceinline__ float tanh_apx(float x) {
    float y;
    asm("tanh.approx.f32 %0, %1;" : "=f"(y) : "f"(x));
    return y;
}

__device__ __forceinline__ unsigned long long ffma2(unsigned long long a,
                                                    unsigned long long b,
                                                    unsigned long long c) {
    unsigned long long d;
    asm("fma.rn.f32x2 %0, %1, %2, %3;" : "=l"(d) : "l"(a), "l"(b), "l"(c));
    return d;
}

__device__ __forceinline__ float f2lo(unsigned long long a) {
    return __uint_as_float((unsigned)(a & 0xffffffffull));
}
__device__ __forceinline__ float f2hi(unsigned long long a) {
    return __uint_as_float((unsigned)(a >> 32));
}

// accurate sigmoid/tanh for the GRU (errors compound over 1024 steps)
__device__ __forceinline__ float sig_acc(float x) {
    float e = __expf(-x);
    return __fdividef(1.0f, 1.0f + e);
}
__device__ __forceinline__ float tanh_acc(float x) {
    float e = __expf(-2.0f * x);
    return __fdividef(1.0f - e, 1.0f + e);
}

__device__ __forceinline__ float block_reduce_max(float v) {
    __shared__ float red[8];
    #pragma unroll
    for (int o = 16; o; o >>= 1) v = fmaxf(v, __shfl_xor_sync(0xffffffffu, v, o));
    if ((threadIdx.x & 31) == 0) red[threadIdx.x >> 5] = v;
    __syncthreads();
    float r = red[0];
    #pragma unroll
    for (int i = 1; i < 8; i++) r = fmaxf(r, red[i]);
    __syncthreads();
    return r;
}

__device__ __forceinline__ float block_reduce_sum(float v) {
    __shared__ float red[8];
    #pragma unroll
    for (int o = 16; o; o >>= 1) v += __shfl_xor_sync(0xffffffffu, v, o);
    if ((threadIdx.x & 31) == 0) red[threadIdx.x >> 5] = v;
    __syncthreads();
    float r = red[0];
    #pragma unroll
    for (int i = 1; i < 8; i++) r += red[i];
    __syncthreads();
    return r;
}

// ---------------- kernel 1: q = X@Wq^T, k = X@Wk^T ----------------
__global__ void __launch_bounds__(256) qk_kernel(const float* __restrict__ X,
                                                 const float* __restrict__ Wq,
                                                 const float* __restrict__ Wk) {
    __shared__ __align__(16) float xs[8][DD];
    const int n0 = blockIdx.x * 8;
    const int tid = threadIdx.x;
    for (int idx = tid; idx < 8 * DD; idx += 256)
        xs[idx >> 7][idx & 127] = X[(n0 + (idx >> 7)) * DD + (idx & 127)];
    __syncthreads();

    const int s = tid >> 7;
    const int d = tid & 127;
    const float4* W4 = (const float4*)((s ? Wk : Wq) + d * DD);
    float acc[8];
    #pragma unroll
    for (int r = 0; r < 8; r++) acc[r] = 0.0f;

    #pragma unroll 8
    for (int c = 0; c < 32; c++) {
        float4 w = W4[c];
        #pragma unroll
        for (int r = 0; r < 8; r++) {
            float4 x = *(const float4*)&xs[r][c * 4];
            acc[r] += w.x * x.x + w.y * x.y + w.z * x.z + w.w * x.w;
        }
    }
    float* dst = s ? g_k : g_q;
    #pragma unroll
    for (int r = 0; r < 8; r++) dst[(n0 + r) * DD + d] = acc[r];
}

// ---------------- kernel 2: attention (scores + softmax + att) ----------------
__global__ void __launch_bounds__(256) att_kernel(const float* __restrict__ X,
                                                  const float* __restrict__ v) {
    __shared__ __align__(16) float q_s[4][DD];
    __shared__ __align__(16) float v_s[DD];
    __shared__ float sc[4][NN];
    __shared__ float inv_s[4];
    __shared__ float part[4][DD];

    const int i0 = blockIdx.x * 4;
    const int tid = threadIdx.x;

    for (int idx = tid; idx < 4 * DD; idx += 256)
        q_s[idx >> 7][idx & 127] = g_q[(i0 + (idx >> 7)) * DD + (idx & 127)];
    if (tid < DD) v_s[tid] = v[tid];
    __syncthreads();

    for (int j = i0 + tid; j < NN; j += 256) {
        const float4* kr = (const float4*)(g_k + j * DD);
        float a0 = 0.f, a1 = 0.f, a2 = 0.f, a3 = 0.f;
        #pragma unroll 4
        for (int c = 0; c < 32; c++) {
            float4 kk = kr[c];
            float4 vv = *(const float4*)&v_s[c * 4];
            float4 q0 = *(const float4*)&q_s[0][c * 4];
            float4 q1 = *(const float4*)&q_s[1][c * 4];
            float4 q2 = *(const float4*)&q_s[2][c * 4];
            float4 q3 = *(const float4*)&q_s[3][c * 4];
            a0 += vv.x * tanh_apx(q0.x + kk.x) + vv.y * tanh_apx(q0.y + kk.y)
                + vv.z * tanh_apx(q0.z + kk.z) + vv.w * tanh_apx(q0.w + kk.w);
            a1 += vv.x * tanh_apx(q1.x + kk.x) + vv.y * tanh_apx(q1.y + kk.y)
                + vv.z * tanh_apx(q1.z + kk.z) + vv.w * tanh_apx(q1.w + kk.w);
            a2 += vv.x * tanh_apx(q2.x + kk.x) + vv.y * tanh_apx(q2.y + kk.y)
                + vv.z * tanh_apx(q2.z + kk.z) + vv.w * tanh_apx(q2.w + kk.w);
            a3 += vv.x * tanh_apx(q3.x + kk.x) + vv.y * tanh_apx(q3.y + kk.y)
                + vv.z * tanh_apx(q3.z + kk.z) + vv.w * tanh_apx(q3.w + kk.w);
        }
        const int jj = j - i0;
        sc[0][jj] = a0; sc[1][jj] = a1; sc[2][jj] = a2; sc[3][jj] = a3;
    }
    __syncthreads();

    const int L = NN - i0;
    for (int r = 0; r < 4; r++) {
        float m = -1e30f;
        for (int idx = tid; idx < L; idx += 256) m = fmaxf(m, sc[r][idx]);
        const float bm = block_reduce_max(m);
        float ssum = 0.f;
        for (int idx = tid; idx < L; idx += 256) {
            float e = (idx < r) ? 0.0f : __expf(sc[r][idx] - bm);
            sc[r][idx] = e;
            ssum += e;
        }
        const float bs = block_reduce_sum(ssum);
        if (tid == 0) inv_s[r] = 1.0f / bs;
    }
    __syncthreads();

    const int d = tid & 127;
    const int s2 = tid >> 7;
    float a[4] = {0.f, 0.f, 0.f, 0.f};
    for (int j = i0 + s2; j < NN; j += 2) {
        const float x = X[j * DD + d];
        const int jj = j - i0;
        a[0] += sc[0][jj] * x;
        a[1] += sc[1][jj] * x;
        a[2] += sc[2][jj] * x;
        a[3] += sc[3][jj] * x;
    }
    if (s2) {
        #pragma unroll
        for (int r = 0; r < 4; r++) part[r][d] = a[r];
    }
    __syncthreads();
    if (!s2) {
        #pragma unroll
        for (int r = 0; r < 4; r++)
            g_att[(i0 + r) * DD + d] = (a[r] + part[r][d]) * inv_s[r];
    }
}

// ---------------- kernel 3: gi = [X, att] @ w_ih^T + b_ih ----------------
__global__ void __launch_bounds__(384) gi_kernel(const float* __restrict__ X,
                                                 const float* __restrict__ w_ih,
                                                 const float* __restrict__ b_ih) {
    __shared__ __align__(16) float in_s[8][2 * DD];
    const int n0 = blockIdx.x * 8;
    const int tid = threadIdx.x;
    for (int idx = tid; idx < 8 * 2 * DD; idx += 384) {
        const int n = idx >> 8, e = idx & 255;
        in_s[n][e] = (e < DD) ? X[(n0 + n) * DD + e] : g_att[(n0 + n) * DD + (e - DD)];
    }
    __syncthreads();

    const float4* w4 = (const float4*)(w_ih + tid * (2 * DD));
    float acc[8];
    #pragma unroll
    for (int r = 0; r < 8; r++) acc[r] = 0.0f;

    #pragma unroll 4
    for (int c = 0; c < 64; c++) {
        float4 w = w4[c];
        #pragma unroll
        for (int r = 0; r < 8; r++) {
            float4 iv = *(const float4*)&in_s[r][c * 4];
            acc[r] += w.x * iv.x + w.y * iv.y + w.z * iv.z + w.w * iv.w;
        }
    }
    const float b = b_ih[tid];
    #pragma unroll
    for (int r = 0; r < 8; r++) g_gi[(n0 + r) * 384 + tid] = acc[r] + b;
}

// ---------------- kernel 4: sequential GRU (single CTA, role-split) ----------------
// Warps 0-3: r-gate rows (t in [0,128)).   Sigmoid applied locally pre-barrier.
// Warps 4-7: z-gate rows (t-128).          Sigmoid applied locally pre-barrier.
// Warps 8-11: n-gate rows (t-256).         Post-barrier: tanh + h update.
// One gi LDG per thread per step (software-pipelined one step ahead).
__global__ void __launch_bounds__(384, 1) gru_kernel(const float* __restrict__ w_hh,
                                                     const float* __restrict__ b_hh,
                                                     float* __restrict__ out) {
    __shared__ __align__(16) float h_s[DD];
    __shared__ float r_s[DD];
    __shared__ float z_s[DD];

    const int t = threadIdx.x;
    const int role = t >> 7;       // 0=r, 1=z, 2=n
    const int g = t & 127;

    unsigned long long w2[64];
    const unsigned long long* wp = (const unsigned long long*)(w_hh + t * DD);
    #pragma unroll
    for (int i = 0; i < 64; i++) w2[i] = wp[i];
    const float bh = b_hh[t];

    if (t < DD) h_s[t] = 0.0f;
    __syncthreads();

    const ulonglong2* h2 = (const ulonglong2*)h_s;

    float gi_cur = g_gi[t];   // step 0 gate input for this thread's own row

    for (int step = 0; step < NN; step++) {
        // prefetch next step's gi (hidden under the matvec)
        float gi_next = 0.0f;
        if (step + 1 < NN) gi_next = g_gi[(step + 1) * 384 + t];

        // s = b_hh[t] + w_hh[t,:] . h   (packed f32x2 MACs, broadcast LDS of h)
        unsigned long long a0 = 0ull, a1 = 0ull, a2 = 0ull, a3 = 0ull;
        #pragma unroll
        for (int i = 0; i < 16; i++) {
            ulonglong2 hA = h2[2 * i];
            ulonglong2 hB = h2[2 * i + 1];
            a0 = ffma2(w2[4 * i + 0], hA.x, a0);
            a1 = ffma2(w2[4 * i + 1], hA.y, a1);
            a2 = ffma2(w2[4 * i + 2], hB.x, a2);
            a3 = ffma2(w2[4 * i + 3], hB.y, a3);
        }
        const float s = ((f2lo(a0) + f2hi(a0)) + (f2lo(a1) + f2hi(a1)))
                      + ((f2lo(a2) + f2hi(a2)) + (f2lo(a3) + f2hi(a3))) + bh;

        // r and z gates finish locally before the barrier (8 warps in parallel)
        if (role == 0) {
            r_s[g] = sig_acc(gi_cur + s);
        } else if (role == 1) {
            z_s[g] = sig_acc(gi_cur + s);
        }
        __syncthreads();   // r_s, z_s visible

        if (role == 2) {
            const float r   = r_s[g];
            const float z   = z_s[g];
            const float nst = tanh_acc(gi_cur + r * s);   // s == gh_n for this row
            const float hv  = (1.0f - z) * nst + z * h_s[g];
            out[step * DD + g] = hv;
            h_s[g] = hv;
        }
        __syncthreads();   // h ready for next step's matvec
        gi_cur = gi_next;
    }
}

// ---------------- launch ----------------
extern "C" void kernel_launch(void* const* d_in, const int* in_sizes, int n_in,
                              void* d_out, int out_size) {
    const float* X    = (const float*)d_in[0];
    const float* Wq   = (const float*)d_in[1];
    const float* Wk   = (const float*)d_in[2];
    const float* v    = (const float*)d_in[3];
    const float* w_ih = (const float*)d_in[4];
    const float* w_hh = (const float*)d_in[5];
    const float* b_ih = (const float*)d_in[6];
    const float* b_hh = (const float*)d_in[7];
    float* out = (float*)d_out;

    qk_kernel<<<NN / 8, 256>>>(X, Wq, Wk);
    att_kernel<<<NN / 4, 256>>>(X, v);
    gi_kernel<<<NN / 8, 384>>>(X, w_ih, b_ih);
    gru_kernel<<<1, 384>>>(w_hh, b_hh, out);
}